// round 2
// baseline (speedup 1.0000x reference)
#include <cuda_runtime.h>

// GLoCELayerOutProp: B=4, T=1024, D=2048, N=8 concepts, S=8, H=8, ETA=1.
//
// Phase 1 (selector): score[n] = (sum_s (W[n,:,s]·(x-mu_n))^2) / ||x-mu_n||^2
//   (algebraically identical to normalizing x_diff first, since normalization
//    is a scalar per (token, concept)).
// gate[n] = sigmoid(slope[n]*(score[n]-center[n])); s = max_n gate; idx = argmax.
// Phase 2: mod_x[h] = upd[idx,:,h]·(x - debias[idx,:]);
//          degen[d] = sum_h dgn[idx,d,h]*mod_x[h];
//          out = (1-s)*x + s*(bias[idx,:] + degen).
//
// Block = 256 threads handles TB=8 tokens (x tile staged in 64KB dynamic smem).
// Phase 1: warp w = concept w, all 8 tokens (amortizes the 64KB/concept W read 8x).
// Phase 2: warp w = token w (independent, no block syncs inside).

#define DD      2048
#define NCON    8
#define SR      8
#define HR      8
#define TB      8
#define NTHREADS 256

__device__ __forceinline__ float warp_sum(float v) {
    #pragma unroll
    for (int o = 16; o > 0; o >>= 1) v += __shfl_xor_sync(0xffffffffu, v, o);
    return v;
}

__global__ void __launch_bounds__(NTHREADS)
gloce_kernel(const float* __restrict__ x,
             const float* __restrict__ Wsel,      // [N,D,S]
             const float* __restrict__ mu,        // [N,D]
             const float* __restrict__ center,    // [N]
             const float* __restrict__ slope,     // [N]
             const float* __restrict__ upd,       // [N,D,H]
             const float* __restrict__ dgn,       // [N,D,H]
             const float* __restrict__ bias_w,    // [N,D]
             const float* __restrict__ debias_w,  // [N,D]
             float* __restrict__ out,
             int n_tokens)
{
    extern __shared__ float xs[];                 // [TB][DD]  (64 KB)
    __shared__ float gates[TB][NCON];

    const int tid  = threadIdx.x;
    const int warp = tid >> 5;
    const int lane = tid & 31;
    const long tok0 = (long)blockIdx.x * TB;

    // ---- stage x tile into smem (coalesced float4) ----
    {
        const float4* xg = reinterpret_cast<const float4*>(x + tok0 * DD);
        float4* xs4 = reinterpret_cast<float4*>(xs);
        #pragma unroll 4
        for (int i = tid; i < TB * DD / 4; i += NTHREADS)
            xs4[i] = xg[i];
    }
    __syncthreads();

    // ---- phase 1: warp `warp` handles concept n = warp for all TB tokens ----
    {
        const int n = warp;
        float acc[TB][SR];
        float nrm[TB];
        #pragma unroll
        for (int t = 0; t < TB; t++) {
            nrm[t] = 0.f;
            #pragma unroll
            for (int s = 0; s < SR; s++) acc[t][s] = 0.f;
        }

        const float* Wn  = Wsel + (long)n * DD * SR;
        const float* mun = mu + n * DD;

        for (int k = 0; k < DD / 32; k++) {
            const int d = lane + 32 * k;
            const float  m  = __ldg(mun + d);
            const float4 wa = *reinterpret_cast<const float4*>(Wn + d * SR);
            const float4 wb = *reinterpret_cast<const float4*>(Wn + d * SR + 4);
            #pragma unroll
            for (int t = 0; t < TB; t++) {
                const float diff = xs[t * DD + d] - m;
                nrm[t]    = fmaf(diff, diff, nrm[t]);
                acc[t][0] = fmaf(wa.x, diff, acc[t][0]);
                acc[t][1] = fmaf(wa.y, diff, acc[t][1]);
                acc[t][2] = fmaf(wa.z, diff, acc[t][2]);
                acc[t][3] = fmaf(wa.w, diff, acc[t][3]);
                acc[t][4] = fmaf(wb.x, diff, acc[t][4]);
                acc[t][5] = fmaf(wb.y, diff, acc[t][5]);
                acc[t][6] = fmaf(wb.z, diff, acc[t][6]);
                acc[t][7] = fmaf(wb.w, diff, acc[t][7]);
            }
        }

        const float cn = center[n];
        const float sn = slope[n];
        #pragma unroll
        for (int t = 0; t < TB; t++) {
            const float nr = warp_sum(nrm[t]);
            float sc = 0.f;
            #pragma unroll
            for (int s = 0; s < SR; s++) {
                const float v = warp_sum(acc[t][s]);
                sc = fmaf(v, v, sc);
            }
            if (lane == 0) {
                const float score = sc / nr;
                const float z = sn * (score - cn);
                gates[t][n] = 1.f / (1.f + expf(-z));
            }
        }
    }
    __syncthreads();

    // ---- phase 2: warp `warp` handles token t = warp ----
    {
        const int t = warp;
        // argmax over concepts (first index wins ties, matching jnp.argmax)
        float best = gates[t][0];
        int bidx = 0;
        #pragma unroll
        for (int n = 1; n < NCON; n++) {
            const float g = gates[t][n];
            if (g > best) { best = g; bidx = n; }
        }
        const float sscale = best;
        const int   n = bidx;

        const float* updn = upd + (long)n * DD * HR;
        const float* dgnn = dgn + (long)n * DD * HR;
        const float* dbn  = debias_w + n * DD;
        const float* bn   = bias_w + n * DD;

        float h[HR];
        #pragma unroll
        for (int j = 0; j < HR; j++) h[j] = 0.f;

        for (int k = 0; k < DD / 32; k++) {
            const int d = lane + 32 * k;
            const float xd = xs[t * DD + d] - __ldg(dbn + d);
            const float4 ua = *reinterpret_cast<const float4*>(updn + d * HR);
            const float4 ub = *reinterpret_cast<const float4*>(updn + d * HR + 4);
            h[0] = fmaf(ua.x, xd, h[0]);
            h[1] = fmaf(ua.y, xd, h[1]);
            h[2] = fmaf(ua.z, xd, h[2]);
            h[3] = fmaf(ua.w, xd, h[3]);
            h[4] = fmaf(ub.x, xd, h[4]);
            h[5] = fmaf(ub.y, xd, h[5]);
            h[6] = fmaf(ub.z, xd, h[6]);
            h[7] = fmaf(ub.w, xd, h[7]);
        }
        #pragma unroll
        for (int j = 0; j < HR; j++) h[j] = warp_sum(h[j]);

        float* outp = out + (tok0 + t) * DD;
        const float oms = 1.f - sscale;
        for (int k = 0; k < DD / 32; k++) {
            const int d = lane + 32 * k;
            const float4 da = *reinterpret_cast<const float4*>(dgnn + d * HR);
            const float4 db = *reinterpret_cast<const float4*>(dgnn + d * HR + 4);
            float dv = da.x * h[0];
            dv = fmaf(da.y, h[1], dv);
            dv = fmaf(da.z, h[2], dv);
            dv = fmaf(da.w, h[3], dv);
            dv = fmaf(db.x, h[4], dv);
            dv = fmaf(db.y, h[5], dv);
            dv = fmaf(db.z, h[6], dv);
            dv = fmaf(db.w, h[7], dv);
            const float res = oms * xs[t * DD + d]
                            + sscale * (__ldg(bn + d) + dv);
            outp[d] = res;
        }
    }
}

extern "C" void kernel_launch(void* const* d_in, const int* in_sizes, int n_in,
                              void* d_out, int out_size) {
    const float* x      = (const float*)d_in[0];
    const float* Wsel   = (const float*)d_in[1];
    const float* mu     = (const float*)d_in[2];
    const float* center = (const float*)d_in[3];
    const float* slope  = (const float*)d_in[4];
    const float* upd    = (const float*)d_in[5];
    const float* dgn    = (const float*)d_in[6];
    const float* bias_w = (const float*)d_in[7];
    const float* debias = (const float*)d_in[8];
    float* out = (float*)d_out;

    const int tokens = in_sizes[0] / DD;          // B*T = 4096
    const int grid   = tokens / TB;               // 512 blocks
    const size_t smem = (size_t)TB * DD * sizeof(float);  // 64 KB

    cudaFuncSetAttribute(gloce_kernel,
                         cudaFuncAttributeMaxDynamicSharedMemorySize,
                         (int)smem);
    gloce_kernel<<<grid, NTHREADS, smem>>>(
        x, Wsel, mu, center, slope, upd, dgn, bias_w, debias, out, tokens);
}